// round 16
// baseline (speedup 1.0000x reference)
#include <cuda_runtime.h>
#include <cstdint>

// ---------------------------------------------------------------------------
// EdgeUpdateMLP: out[e] = W2 @ relu(W1 @ [ef[e]|nf[src]|nf[tgt]] + b1) + b2
// Warp-level mma.sync tf32 (compute_103-safe), fused 2-layer MLP,
// 128-edge tiles, persistent CTAs, weights resident in SMEM.
// ---------------------------------------------------------------------------

#define THREADS 256

// float strides (pad +4 => stride % 32 == 4 -> conflict-free fragment LDS)
#define XS_STR 164   // x tile: 128 x 160
#define HS_STR 132   // h tile: 128 x 128 (reuses x region)
#define W1_STR 164   // W1: 128 x 160
#define W2_STR 132   // W2:  64 x 128

#define OFF_IDX 0                          // 256 ints
#define OFF_B1  1024                       // 128 floats
#define OFF_B2  1536                       // 64 floats
#define OFF_X   2048                       // 128*164*4 = 83968 B
#define OFF_W1  (OFF_X  + 128 * XS_STR * 4)  // 86016
#define OFF_W2  (OFF_W1 + 128 * W1_STR * 4)  // 169984
#define SMEM_BYTES (OFF_W2 + 64 * W2_STR * 4) // 203776

// ---------------------------------------------------------------------------
static __device__ __forceinline__ uint32_t f2tf32(float x) {
    uint32_t u;
    asm("cvt.rna.tf32.f32 %0, %1;" : "=r"(u) : "f"(x));
    return u;
}

// D += A*B  (m16n8k8, row.col, tf32 in / f32 accum)
static __device__ __forceinline__ void mma8(float* c, const uint32_t* a,
                                            uint32_t b0, uint32_t b1) {
    asm volatile(
        "mma.sync.aligned.m16n8k8.row.col.f32.tf32.tf32.f32 "
        "{%0,%1,%2,%3}, {%4,%5,%6,%7}, {%8,%9}, {%0,%1,%2,%3};"
        : "+f"(c[0]), "+f"(c[1]), "+f"(c[2]), "+f"(c[3])
        : "r"(a[0]), "r"(a[1]), "r"(a[2]), "r"(a[3]), "r"(b0), "r"(b1));
}

extern __shared__ __align__(16) char smem[];

__global__ __launch_bounds__(THREADS, 1)
void edge_mlp_kernel(const int* __restrict__ eidx,
                     const float* __restrict__ nf,
                     const float* __restrict__ ef,
                     const float* __restrict__ W1,
                     const float* __restrict__ b1,
                     const float* __restrict__ W2,
                     const float* __restrict__ b2,
                     float* __restrict__ out,
                     int E, int ntiles) {
    const int tid  = threadIdx.x;
    const int wid  = tid >> 5;
    const int lane = tid & 31;
    const int g    = lane >> 2;   // group id (0..7)
    const int t4   = lane & 3;    // thread-in-group (0..3)
    const int wm   = wid & 3;     // warp M slot (0..3) -> 32 edge rows
    const int wn   = wid >> 2;    // warp N slot (0..1)

    int*       ix  = (int*)(smem + OFF_IDX);
    float*     b1s = (float*)(smem + OFF_B1);
    float*     b2s = (float*)(smem + OFF_B2);
    uint32_t*  Xs  = (uint32_t*)(smem + OFF_X);    // also H after GEMM1
    uint32_t*  W1s = (uint32_t*)(smem + OFF_W1);
    uint32_t*  W2s = (uint32_t*)(smem + OFF_W2);

    // ---- load weights once (tf32-converted) ----
    for (int idx = tid; idx < 128 * 40; idx += THREADS) {   // W1: [128][160]
        int row = idx / 40, k = (idx - row * 40) << 2;
        float4 v = *(const float4*)(W1 + (size_t)row * 160 + k);
        *(uint4*)(W1s + row * W1_STR + k) =
            make_uint4(f2tf32(v.x), f2tf32(v.y), f2tf32(v.z), f2tf32(v.w));
    }
    for (int idx = tid; idx < 64 * 32; idx += THREADS) {    // W2: [64][128]
        int row = idx / 32, k = (idx - row * 32) << 2;
        float4 v = *(const float4*)(W2 + (size_t)row * 128 + k);
        *(uint4*)(W2s + row * W2_STR + k) =
            make_uint4(f2tf32(v.x), f2tf32(v.y), f2tf32(v.z), f2tf32(v.w));
    }
    if (tid < 128) b1s[tid] = b1[tid];
    if (tid < 64)  b2s[tid] = b2[tid];
    __syncthreads();

    for (int tile = blockIdx.x; tile < ntiles; tile += gridDim.x) {
        const int ebase = tile * 128;

        // ---- stage edge indices: ix[0..127]=src, ix[128..255]=tgt ----
        {
            int r = tid & 127;
            int e = ebase + r;
            int v = 0;
            if (e < E) v = (tid < 128) ? eidx[e] : eidx[(size_t)E + e];
            ix[tid] = v;
        }
        __syncthreads();

        // ---- gather x tile: [ef(32) | nf[src](64) | nf[tgt](64)] ----
        #pragma unroll
        for (int i = 0; i < 20; i++) {
            int idx = tid + i * THREADS;          // 0..5119
            int row = idx / 40;
            int k   = (idx - row * 40) << 2;
            int e   = ebase + row;
            float4 v = make_float4(0.f, 0.f, 0.f, 0.f);
            if (e < E) {
                if (k < 32)      v = *(const float4*)(ef + (size_t)e * 32 + k);
                else if (k < 96) v = *(const float4*)(nf + (size_t)ix[row] * 64 + (k - 32));
                else             v = *(const float4*)(nf + (size_t)ix[128 + row] * 64 + (k - 96));
            }
            *(uint4*)(Xs + row * XS_STR + k) =
                make_uint4(f2tf32(v.x), f2tf32(v.y), f2tf32(v.z), f2tf32(v.w));
        }
        __syncthreads();

        // ---- GEMM1: H[128,128] = X[128,160] @ W1^T ; warp tile 32x64 ----
        float acc[2][8][4];
        #pragma unroll
        for (int mt = 0; mt < 2; mt++)
            #pragma unroll
            for (int nt = 0; nt < 8; nt++)
                #pragma unroll
                for (int q = 0; q < 4; q++) acc[mt][nt][q] = 0.f;

        #pragma unroll
        for (int ks = 0; ks < 20; ks++) {
            const int k0 = ks * 8;
            uint32_t a[2][4];
            #pragma unroll
            for (int mt = 0; mt < 2; mt++) {
                const uint32_t* p = Xs + (wm * 32 + mt * 16 + g) * XS_STR + k0 + t4;
                a[mt][0] = p[0];
                a[mt][1] = p[8 * XS_STR];
                a[mt][2] = p[4];
                a[mt][3] = p[8 * XS_STR + 4];
            }
            #pragma unroll
            for (int nt = 0; nt < 8; nt++) {
                const uint32_t* p = W1s + (wn * 64 + nt * 8 + g) * W1_STR + k0 + t4;
                uint32_t b0 = p[0], bB = p[4];
                mma8(acc[0][nt], a[0], b0, bB);
                mma8(acc[1][nt], a[1], b0, bB);
            }
        }
        __syncthreads();   // all Xs reads done before H overwrites it

        // ---- epilogue 1: h = relu(acc + b1) -> SMEM (tf32) ----
        uint32_t* Hs = Xs;
        #pragma unroll
        for (int mt = 0; mt < 2; mt++) {
            const int r0 = wm * 32 + mt * 16 + g;
            #pragma unroll
            for (int nt = 0; nt < 8; nt++) {
                const int col = wn * 64 + nt * 8 + 2 * t4;
                float bi0 = b1s[col], bi1 = b1s[col + 1];
                float h0 = fmaxf(acc[mt][nt][0] + bi0, 0.f);
                float h1 = fmaxf(acc[mt][nt][1] + bi1, 0.f);
                float h2 = fmaxf(acc[mt][nt][2] + bi0, 0.f);
                float h3 = fmaxf(acc[mt][nt][3] + bi1, 0.f);
                *(uint2*)(Hs + r0 * HS_STR + col)       = make_uint2(f2tf32(h0), f2tf32(h1));
                *(uint2*)(Hs + (r0 + 8) * HS_STR + col) = make_uint2(f2tf32(h2), f2tf32(h3));
            }
        }
        __syncthreads();

        // ---- GEMM2: O[128,64] = H[128,128] @ W2^T ; warp tile 32x32 ----
        float acc2[2][4][4];
        #pragma unroll
        for (int mt = 0; mt < 2; mt++)
            #pragma unroll
            for (int nt = 0; nt < 4; nt++)
                #pragma unroll
                for (int q = 0; q < 4; q++) acc2[mt][nt][q] = 0.f;

        #pragma unroll
        for (int ks = 0; ks < 16; ks++) {
            const int k0 = ks * 8;
            uint32_t a[2][4];
            #pragma unroll
            for (int mt = 0; mt < 2; mt++) {
                const uint32_t* p = Hs + (wm * 32 + mt * 16 + g) * HS_STR + k0 + t4;
                a[mt][0] = p[0];
                a[mt][1] = p[8 * HS_STR];
                a[mt][2] = p[4];
                a[mt][3] = p[8 * HS_STR + 4];
            }
            #pragma unroll
            for (int nt = 0; nt < 4; nt++) {
                const uint32_t* p = W2s + (wn * 32 + nt * 8 + g) * W2_STR + k0 + t4;
                uint32_t b0 = p[0], bB = p[4];
                mma8(acc2[0][nt], a[0], b0, bB);
                mma8(acc2[1][nt], a[1], b0, bB);
            }
        }

        // ---- epilogue 2: out = acc2 + b2 (global only) ----
        #pragma unroll
        for (int mt = 0; mt < 2; mt++) {
            const int r0 = wm * 32 + mt * 16 + g;
            const int e0 = ebase + r0;
            #pragma unroll
            for (int nt = 0; nt < 4; nt++) {
                const int col = wn * 32 + nt * 8 + 2 * t4;
                float bi0 = b2s[col], bi1 = b2s[col + 1];
                if (e0 < E)
                    *(float2*)(out + (size_t)e0 * 64 + col) =
                        make_float2(acc2[mt][nt][0] + bi0, acc2[mt][nt][1] + bi1);
                if (e0 + 8 < E)
                    *(float2*)(out + (size_t)(e0 + 8) * 64 + col) =
                        make_float2(acc2[mt][nt][2] + bi0, acc2[mt][nt][3] + bi1);
            }
        }
        __syncthreads();   // H/ix reads done before next tile's staging
    }
}

// ---------------------------------------------------------------------------
extern "C" void kernel_launch(void* const* d_in, const int* in_sizes, int n_in,
                              void* d_out, int out_size) {
    const int*   eidx = (const int*)d_in[0];
    const float* nf   = (const float*)d_in[1];
    const float* ef   = (const float*)d_in[2];
    const float* W1   = (const float*)d_in[3];
    const float* b1   = (const float*)d_in[4];
    const float* W2   = (const float*)d_in[5];
    const float* b2   = (const float*)d_in[6];
    float* out = (float*)d_out;

    int E = in_sizes[0] / 2;
    int ntiles = (E + 127) / 128;

    cudaFuncSetAttribute(edge_mlp_kernel,
                         cudaFuncAttributeMaxDynamicSharedMemorySize, SMEM_BYTES);

    int sms = 0;
    cudaDeviceGetAttribute(&sms, cudaDevAttrMultiProcessorCount, 0);
    if (sms <= 0) sms = 148;
    int grid = (ntiles < sms) ? ntiles : sms;

    edge_mlp_kernel<<<grid, THREADS, SMEM_BYTES>>>(eidx, nf, ef, W1, b1, W2, b2,
                                                   out, E, ntiles);
}

// round 17
// speedup vs baseline: 1.8205x; 1.8205x over previous
#include <cuda_runtime.h>
#include <cstdint>

// ---------------------------------------------------------------------------
// EdgeUpdateMLP: out[e] = W2 @ relu(W1 @ [ef[e]|nf[src]|nf[tgt]] + b1) + b2
// mma.sync tf32, fused 2-layer MLP, 64-edge tiles, cp.async double-buffered
// gather pipeline, weights resident in SMEM, persistent CTAs.
// ---------------------------------------------------------------------------

#define THREADS 256

// float strides (pad so stride % 32 == 4 -> conflict-free fragment LDS)
#define XS_STR 164   // X tile: 64 x 160 (reused as H: 64 x 128 w/ HS_STR)
#define HS_STR 132
#define W1_STR 164   // W1: 128 x 160
#define W2_STR 132   // W2:  64 x 128

#define OFF_B1 0                              // 128 floats
#define OFF_B2 512                            // 64 floats
#define OFF_X0 1024
#define X_BYTES (64 * XS_STR * 4)             // 41984
#define OFF_X1 (OFF_X0 + X_BYTES)
#define OFF_W1 (OFF_X1 + X_BYTES)             // 84992
#define OFF_W2 (OFF_W1 + 128 * W1_STR * 4)    // 168960
#define SMEM_BYTES (OFF_W2 + 64 * W2_STR * 4) // 202752

// ---------------------------------------------------------------------------
static __device__ __forceinline__ uint32_t f2tf32(float x) {
    uint32_t u;
    asm("cvt.rna.tf32.f32 %0, %1;" : "=r"(u) : "f"(x));
    return u;
}
static __device__ __forceinline__ uint32_t smem_u32(const void* p) {
    uint32_t a;
    asm("{ .reg .u64 t; cvta.to.shared.u64 t, %1; cvt.u32.u64 %0, t; }" : "=r"(a) : "l"(p));
    return a;
}
// D += A*B  (m16n8k8, row.col, tf32 in / f32 accum)
static __device__ __forceinline__ void mma8(float* c, const uint32_t* a,
                                            uint32_t b0, uint32_t b1) {
    asm volatile(
        "mma.sync.aligned.m16n8k8.row.col.f32.tf32.tf32.f32 "
        "{%0,%1,%2,%3}, {%4,%5,%6,%7}, {%8,%9}, {%0,%1,%2,%3};"
        : "+f"(c[0]), "+f"(c[1]), "+f"(c[2]), "+f"(c[3])
        : "r"(a[0]), "r"(a[1]), "r"(a[2]), "r"(a[3]), "r"(b0), "r"(b1));
}
#define CP_ASYNC16(s, g) asm volatile("cp.async.cg.shared.global [%0], [%1], 16;" :: "r"(s), "l"(g) : "memory")
#define CP_COMMIT()      asm volatile("cp.async.commit_group;" ::: "memory")
#define CP_WAIT1()       asm volatile("cp.async.wait_group 1;" ::: "memory")

extern __shared__ __align__(16) char smem[];

__global__ __launch_bounds__(THREADS, 1)
void edge_mlp_kernel(const int* __restrict__ eidx,
                     const float* __restrict__ nf,
                     const float* __restrict__ ef,
                     const float* __restrict__ W1,
                     const float* __restrict__ b1,
                     const float* __restrict__ W2,
                     const float* __restrict__ b2,
                     float* __restrict__ out,
                     int E, int ntiles) {
    const int tid  = threadIdx.x;
    const int wid  = tid >> 5;
    const int lane = tid & 31;
    const int g    = lane >> 2;
    const int t4   = lane & 3;
    const int wm   = wid & 1;    // 2 M slots (32 edge rows each)
    const int wn   = wid >> 1;   // 4 N slots

    float*    b1s = (float*)(smem + OFF_B1);
    float*    b2s = (float*)(smem + OFF_B2);
    uint32_t* W1s = (uint32_t*)(smem + OFF_W1);
    uint32_t* W2s = (uint32_t*)(smem + OFF_W2);
    const uint32_t sbase = smem_u32(smem);

    // ---- load weights once (tf32-converted) ----
    for (int idx = tid; idx < 128 * 40; idx += THREADS) {
        int row = idx / 40, k = (idx - row * 40) << 2;
        float4 v = *(const float4*)(W1 + (size_t)row * 160 + k);
        *(uint4*)(W1s + row * W1_STR + k) =
            make_uint4(f2tf32(v.x), f2tf32(v.y), f2tf32(v.z), f2tf32(v.w));
    }
    for (int idx = tid; idx < 64 * 32; idx += THREADS) {
        int row = idx / 32, k = (idx - row * 32) << 2;
        float4 v = *(const float4*)(W2 + (size_t)row * 128 + k);
        *(uint4*)(W2s + row * W2_STR + k) =
            make_uint4(f2tf32(v.x), f2tf32(v.y), f2tf32(v.z), f2tf32(v.w));
    }
    if (tid < 128) b1s[tid] = b1[tid];
    if (tid < 64)  b2s[tid] = b2[tid];

    // ---- per-thread gather descriptors (tile-invariant) ----
    // item i covers (row, k4): 16B of X row. kind 0=ef, 1=nf[src], 2=nf[tgt].
    int      desc[10];   // row | goff<<8 | kind<<20   (goff in floats)
    uint32_t xoff[10];   // smem byte offset within an X buffer
    #pragma unroll
    for (int i = 0; i < 10; i++) {
        int idx = tid + i * THREADS;
        int row = idx / 40, k4 = idx - row * 40;
        int kind, goff;
        if (k4 < 8)       { kind = 0; goff = k4 * 4; }
        else if (k4 < 24) { kind = 1; goff = (k4 - 8) * 4; }
        else              { kind = 2; goff = (k4 - 24) * 4; }
        desc[i] = row | (goff << 8) | (kind << 20);
        xoff[i] = (uint32_t)((row * XS_STR + k4 * 4) * 4);
    }

    const int grid = gridDim.x;
    int nidx[10];

    auto prefetch_idx = [&](int tt) {
        #pragma unroll
        for (int i = 0; i < 10; i++) {
            int kind = desc[i] >> 20;
            if (kind == 0) { nidx[i] = 0; continue; }
            int e = tt * 64 + (desc[i] & 0xFF);
            if (e >= E) e = E - 1;
            nidx[i] = (kind == 1) ? eidx[e] : eidx[(size_t)E + e];
        }
    };
    auto issue_gather = [&](int tt, uint32_t xb) {
        #pragma unroll
        for (int i = 0; i < 10; i++) {
            int kind = desc[i] >> 20;
            int goff = (desc[i] >> 8) & 0xFFF;
            int e = tt * 64 + (desc[i] & 0xFF);
            if (e >= E) e = E - 1;
            const float* gp = (kind == 0) ? ef + (size_t)e * 32 + goff
                                          : nf + (size_t)nidx[i] * 64 + goff;
            CP_ASYNC16(xb + xoff[i], gp);
        }
    };

    // ---- pipeline prologue ----
    const int t0 = blockIdx.x;
    prefetch_idx(t0);
    issue_gather(t0, sbase + OFF_X0);
    CP_COMMIT();
    prefetch_idx(t0 + grid < ntiles ? t0 + grid : t0);

    int buf = 0;
    for (int tile = t0; tile < ntiles; tile += grid) {
        // issue next tile's gather into the other buffer (its previous
        // contents — H of tile-1 — were fully consumed before loop-end sync)
        int tn = tile + grid; if (tn >= ntiles) tn = tile;
        issue_gather(tn, sbase + (buf ? OFF_X0 : OFF_X1));
        CP_COMMIT();
        { int tnn = tn + grid; if (tnn >= ntiles) tnn = tn; prefetch_idx(tnn); }

        CP_WAIT1();          // current tile's fills complete (next may be in flight)
        __syncthreads();     // cross-thread visibility

        uint32_t* Xb = (uint32_t*)(smem + (buf ? OFF_X1 : OFF_X0));
        const int ebase = tile * 64;

        // ---- GEMM1: H[64,128] = X[64,160] @ W1^T ; warp tile 32x32 ----
        float acc[2][4][4];
        #pragma unroll
        for (int mt = 0; mt < 2; mt++)
            #pragma unroll
            for (int nt = 0; nt < 4; nt++)
                #pragma unroll
                for (int q = 0; q < 4; q++) acc[mt][nt][q] = 0.f;

        #pragma unroll
        for (int ks = 0; ks < 20; ks++) {
            const int k0 = ks * 8;
            uint32_t a[2][4];
            #pragma unroll
            for (int mt = 0; mt < 2; mt++) {
                const uint32_t* p = Xb + (wm * 32 + mt * 16 + g) * XS_STR + k0 + t4;
                a[mt][0] = p[0];
                a[mt][1] = p[8 * XS_STR];
                a[mt][2] = p[4];
                a[mt][3] = p[8 * XS_STR + 4];
            }
            #pragma unroll
            for (int nt = 0; nt < 4; nt++) {
                const uint32_t* p = W1s + (wn * 32 + nt * 8 + g) * W1_STR + k0 + t4;
                uint32_t b0 = p[0], bB = p[4];
                mma8(acc[0][nt], a[0], b0, bB);
                mma8(acc[1][nt], a[1], b0, bB);
            }
        }
        __syncthreads();   // all X reads done before H overwrites the buffer

        // ---- epilogue 1: h = relu(acc + b1) -> same buffer as H (tf32) ----
        #pragma unroll
        for (int mt = 0; mt < 2; mt++) {
            const int r0 = wm * 32 + mt * 16 + g;
            #pragma unroll
            for (int nt = 0; nt < 4; nt++) {
                const int col = wn * 32 + nt * 8 + 2 * t4;
                float bi0 = b1s[col], bi1 = b1s[col + 1];
                float h0 = fmaxf(acc[mt][nt][0] + bi0, 0.f);
                float h1 = fmaxf(acc[mt][nt][1] + bi1, 0.f);
                float h2 = fmaxf(acc[mt][nt][2] + bi0, 0.f);
                float h3 = fmaxf(acc[mt][nt][3] + bi1, 0.f);
                *(uint2*)(Xb + r0 * HS_STR + col)       = make_uint2(f2tf32(h0), f2tf32(h1));
                *(uint2*)(Xb + (r0 + 8) * HS_STR + col) = make_uint2(f2tf32(h2), f2tf32(h3));
            }
        }
        __syncthreads();

        // ---- GEMM2: O[64,64] = H[64,128] @ W2^T ; warp tile 32x16 ----
        float acc2[2][2][4];
        #pragma unroll
        for (int mt = 0; mt < 2; mt++)
            #pragma unroll
            for (int nt = 0; nt < 2; nt++)
                #pragma unroll
                for (int q = 0; q < 4; q++) acc2[mt][nt][q] = 0.f;

        #pragma unroll
        for (int ks = 0; ks < 16; ks++) {
            const int k0 = ks * 8;
            uint32_t a[2][4];
            #pragma unroll
            for (int mt = 0; mt < 2; mt++) {
                const uint32_t* p = Xb + (wm * 32 + mt * 16 + g) * HS_STR + k0 + t4;
                a[mt][0] = p[0];
                a[mt][1] = p[8 * HS_STR];
                a[mt][2] = p[4];
                a[mt][3] = p[8 * HS_STR + 4];
            }
            #pragma unroll
            for (int nt = 0; nt < 2; nt++) {
                const uint32_t* p = W2s + (wn * 16 + nt * 8 + g) * W2_STR + k0 + t4;
                uint32_t b0 = p[0], bB = p[4];
                mma8(acc2[0][nt], a[0], b0, bB);
                mma8(acc2[1][nt], a[1], b0, bB);
            }
        }

        // ---- epilogue 2: out = acc2 + b2 ----
        #pragma unroll
        for (int mt = 0; mt < 2; mt++) {
            const int r0 = wm * 32 + mt * 16 + g;
            const int e0 = ebase + r0;
            #pragma unroll
            for (int nt = 0; nt < 2; nt++) {
                const int col = wn * 16 + nt * 8 + 2 * t4;
                float bi0 = b2s[col], bi1 = b2s[col + 1];
                if (e0 < E)
                    *(float2*)(out + (size_t)e0 * 64 + col) =
                        make_float2(acc2[mt][nt][0] + bi0, acc2[mt][nt][1] + bi1);
                if (e0 + 8 < E)
                    *(float2*)(out + (size_t)(e0 + 8) * 64 + col) =
                        make_float2(acc2[mt][nt][2] + bi0, acc2[mt][nt][3] + bi1);
            }
        }
        __syncthreads();   // H reads done before next iter's cp.async refills buf
        buf ^= 1;
    }
}

// ---------------------------------------------------------------------------
extern "C" void kernel_launch(void* const* d_in, const int* in_sizes, int n_in,
                              void* d_out, int out_size) {
    const int*   eidx = (const int*)d_in[0];
    const float* nf   = (const float*)d_in[1];
    const float* ef   = (const float*)d_in[2];
    const float* W1   = (const float*)d_in[3];
    const float* b1   = (const float*)d_in[4];
    const float* W2   = (const float*)d_in[5];
    const float* b2   = (const float*)d_in[6];
    float* out = (float*)d_out;

    int E = in_sizes[0] / 2;
    int ntiles = (E + 63) / 64;

    cudaFuncSetAttribute(edge_mlp_kernel,
                         cudaFuncAttributeMaxDynamicSharedMemorySize, SMEM_BYTES);

    int sms = 0;
    cudaDeviceGetAttribute(&sms, cudaDevAttrMultiProcessorCount, 0);
    if (sms <= 0) sms = 148;
    int grid = (ntiles < sms) ? ntiles : sms;

    edge_mlp_kernel<<<grid, THREADS, SMEM_BYTES>>>(eidx, nf, ef, W1, b1, W2, b2,
                                                   out, E, ntiles);
}